// round 4
// baseline (speedup 1.0000x reference)
#include <cuda_runtime.h>
#include <cstdint>

#define BQ 8
#define CQ 32
#define KQ 512
#define IT 8            // i-rows per block in kernel 1 (4 f32x2 pairs)
#define NPAIR (IT/2)

// Uncertain-decision list (worst case B*K*K entries)
__device__ uint32_t g_cnt;
__device__ uint2    g_ent[BQ * KQ * KQ];   // .x = (b<<18)|(i<<9)|j, .y = logit bits

// ---------------------------------------------------------------------------
// f32x2 packed helpers. Everything is expressed as fma.rn.f32x2 (FFMA2):
//   add(a,b) == fma(a, 1.0, b)   (a*1 exact, single rn on the sum)
//   mul(a,b) == fma(a, b, +0)    (rn(ab); -0 -> +0 only, annihilated by squares)
// Each lane is rn-rounded exactly like the scalar reference sequence.
// ---------------------------------------------------------------------------
__device__ __forceinline__ uint64_t pack2(float lo, float hi) {
    uint64_t r; asm("mov.b64 %0, {%1,%2};" : "=l"(r) : "f"(lo), "f"(hi)); return r;
}
__device__ __forceinline__ uint64_t fma2(uint64_t a, uint64_t b, uint64_t c) {
    uint64_t r; asm("fma.rn.f32x2 %0, %1, %2, %3;" : "=l"(r) : "l"(a), "l"(b), "l"(c));
    return r;
}
__device__ __forceinline__ void unpack2(uint64_t v, float& lo, float& hi) {
    asm("mov.b64 {%0,%1}, %2;" : "=f"(lo), "=f"(hi) : "l"(v));
}

#define ONE2  0x3F8000003F800000ull
#define ZERO2 0x0000000000000000ull

// ---------------------------------------------------------------------------
// Threefry-2x32, key (0, 42); partitionable scheme: bits(idx) = o0 ^ o1 of
// threefry(key, (0, idx)).
// ---------------------------------------------------------------------------
__device__ __forceinline__ uint32_t rotl32(uint32_t x, int r) {
    return (x << r) | (x >> (32 - r));
}
__device__ __forceinline__ void threefry_0_42(uint32_t x0, uint32_t x1,
                                              uint32_t& o0, uint32_t& o1) {
    const uint32_t ks0 = 0u, ks1 = 42u, ks2 = 0u ^ 42u ^ 0x1BD11BDAu;
    x0 += ks0; x1 += ks1;
    x0 += x1; x1 = rotl32(x1, 13); x1 ^= x0;
    x0 += x1; x1 = rotl32(x1, 15); x1 ^= x0;
    x0 += x1; x1 = rotl32(x1, 26); x1 ^= x0;
    x0 += x1; x1 = rotl32(x1, 6);  x1 ^= x0;
    x0 += ks1; x1 += ks2 + 1u;
    x0 += x1; x1 = rotl32(x1, 17); x1 ^= x0;
    x0 += x1; x1 = rotl32(x1, 29); x1 ^= x0;
    x0 += x1; x1 = rotl32(x1, 16); x1 ^= x0;
    x0 += x1; x1 = rotl32(x1, 24); x1 ^= x0;
    x0 += ks2; x1 += ks0 + 2u;
    x0 += x1; x1 = rotl32(x1, 13); x1 ^= x0;
    x0 += x1; x1 = rotl32(x1, 15); x1 ^= x0;
    x0 += x1; x1 = rotl32(x1, 26); x1 ^= x0;
    x0 += x1; x1 = rotl32(x1, 6);  x1 ^= x0;
    x0 += ks0; x1 += ks1 + 3u;
    x0 += x1; x1 = rotl32(x1, 17); x1 ^= x0;
    x0 += x1; x1 = rotl32(x1, 29); x1 ^= x0;
    x0 += x1; x1 = rotl32(x1, 16); x1 ^= x0;
    x0 += x1; x1 = rotl32(x1, 24); x1 ^= x0;
    x0 += ks1; x1 += ks2 + 4u;
    x0 += x1; x1 = rotl32(x1, 13); x1 ^= x0;
    x0 += x1; x1 = rotl32(x1, 15); x1 ^= x0;
    x0 += x1; x1 = rotl32(x1, 26); x1 ^= x0;
    x0 += x1; x1 = rotl32(x1, 6);  x1 ^= x0;
    x0 += ks2; x1 += ks0 + 5u;
    o0 = x0; o1 = x1;
}
__device__ __forceinline__ uint32_t jax_bits_partitionable(uint32_t idx) {
    uint32_t o0, o1;
    threefry_0_42(0u, idx, o0, o1);
    return o0 ^ o1;
}
__device__ __forceinline__ float gumbel_from_bits(uint32_t bits) {
    float f = __uint_as_float((bits >> 9) | 0x3F800000u) - 1.0f;
    float u = fmaxf(__fadd_rn(f, 1e-10f), 1e-10f);
    return -logf(-logf(u));
}

// ---------------------------------------------------------------------------
// Kernel 1: logits + uncertain-list compaction.
// grid (KQ/IT, BQ), 512 threads (thread = j). FFMA2 over i-row pairs.
// ---------------------------------------------------------------------------
__global__ void __launch_bounds__(KQ)
k_logit(const float* __restrict__ amp, const float* __restrict__ ph,
        const float* __restrict__ A,
        const float* __restrict__ wa_p, const float* __restrict__ wp_p) {
    const int b  = blockIdx.y;
    const int i0 = blockIdx.x * IT;
    const int j  = threadIdx.x;

    // smem tiles: [c] row of 4 u64 (8 floats, t contiguous) -> 32B rows
    __shared__ uint64_t s_a2[CQ][NPAIR];
    __shared__ uint64_t s_p2[CQ][NPAIR];
    __shared__ float    s_max[IT][16];
    __shared__ uint32_t s_cnt;
    __shared__ uint32_t s_base;

    const float wa = wa_p[0];
    const float wp = wp_p[0];

    if (threadIdx.x == 0) s_cnt = 0;
    if (threadIdx.x < IT * CQ) {
        int t = threadIdx.x % IT;
        int c = threadIdx.x / IT;
        ((float*)&s_a2[c][0])[t] = amp[(b * CQ + c) * KQ + i0 + t];
        ((float*)&s_p2[c][0])[t] = ph [(b * CQ + c) * KQ + i0 + t];
    }
    __syncthreads();

    const float Ajj = A[j * KQ + j];
    const uint64_t wa2 = pack2(wa, wa);
    const uint64_t wp2 = pack2(wp, wp);
    const uint64_t A2  = pack2(Ajj, Ajj);

    uint64_t acc2[NPAIR];
#pragma unroll
    for (int p = 0; p < NPAIR; p++) acc2[p] = 0ull;

    const float* ap = amp + (size_t)b * CQ * KQ + j;
    const float* pp = ph  + (size_t)b * CQ * KQ + j;

#pragma unroll 4
    for (int c = 0; c < CQ; c++) {
        float aj = ap[c * KQ];
        float pj = pp[c * KQ];
        uint64_t naj2 = pack2(-aj, -aj);
        uint64_t npj2 = pack2(-pj, -pj);
        // 32B smem row -> two 16B vector loads
        ulonglong2 va0 = *(const ulonglong2*)&s_a2[c][0];
        ulonglong2 va1 = *(const ulonglong2*)&s_a2[c][2];
        ulonglong2 vp0 = *(const ulonglong2*)&s_p2[c][0];
        ulonglong2 vp1 = *(const ulonglong2*)&s_p2[c][2];
        uint64_t sa[NPAIR] = {va0.x, va0.y, va1.x, va1.y};
        uint64_t sp[NPAIR] = {vp0.x, vp0.y, vp1.x, vp1.y};
#pragma unroll
        for (int p = 0; p < NPAIR; p++) {
            // exact replication: ad = ai - aj, pd = pi - pj,
            // f = rn(rn(wa*ad) + rn(wp*pd)), tt = rn(f*Ajj), acc = rn(acc + rn(tt*tt))
            uint64_t ad2 = fma2(sa[p], ONE2, naj2);
            uint64_t pd2 = fma2(sp[p], ONE2, npj2);
            uint64_t t0  = fma2(wa2, ad2, ZERO2);
            uint64_t t1  = fma2(wp2, pd2, ZERO2);
            uint64_t f2  = fma2(t0, ONE2, t1);
            uint64_t tt2 = fma2(f2, A2, ZERO2);
            uint64_t sq2 = fma2(tt2, tt2, ZERO2);
            acc2[p] = fma2(sq2, ONE2, acc2[p]);
        }
    }

    float acc[IT], ed[IT];
#pragma unroll
    for (int p = 0; p < NPAIR; p++) unpack2(acc2[p], acc[2 * p], acc[2 * p + 1]);

#pragma unroll
    for (int t = 0; t < IT; t++) {
        float d = __fadd_rn(acc[t], 1e-10f);
        float e = __fdiv_rn(1.0f, d);
        if (j == i0 + t) e = 0.0f;           // offdiag mask before the max
        ed[t] = e;
        float m = e;
#pragma unroll
        for (int o = 16; o > 0; o >>= 1)
            m = fmaxf(m, __shfl_xor_sync(0xFFFFFFFFu, m, o));
        if ((threadIdx.x & 31) == 0) s_max[t][threadIdx.x >> 5] = m;
    }
    __syncthreads();

    float lg[IT];
    int nunc = 0;
    int tlist[IT];
#pragma unroll
    for (int t = 0; t < IT; t++) {
        float m = s_max[t][0];
#pragma unroll
        for (int w = 1; w < 16; w++) m = fmaxf(m, s_max[t][w]);

        if (j == i0 + t) {
            // diag: p = 0.99 exactly
            float l = logf(__fdiv_rn(0.99f, __fsub_rn(1.0f, 0.99f)));
            lg[t] = l; tlist[nunc++] = t;
        } else if (ed[t] > __fmul_rn(4.5e-5f, m)) {
            // prefilter: e <= 4.5e-5*m provably implies 2l <= -20 (certain 0),
            // so only these candidates need the div + logf + exact test.
            float p = __fmul_rn(__fdiv_rn(ed[t], m), 0.99f);
            float l = logf(__fdiv_rn(p, __fsub_rn(1.0f, p)));
            if (!(__fadd_rn(l, l) <= -20.0f)) { lg[t] = l; tlist[nunc] = t; nunc++; }
        }
    }

    int rank = 0;
    if (nunc > 0) rank = atomicAdd(&s_cnt, (uint32_t)nunc);
    __syncthreads();
    if (threadIdx.x == 0 && s_cnt > 0) s_base = atomicAdd(&g_cnt, s_cnt);
    __syncthreads();

    for (int q = 0; q < nunc; q++) {
        int t = tlist[q];
        uint2 ent;
        ent.x = ((uint32_t)b << 18) | ((uint32_t)(i0 + t) << 9) | (uint32_t)j;
        ent.y = __float_as_uint(lg[t]);
        g_ent[s_base + rank + q] = ent;
    }
}

// ---------------------------------------------------------------------------
// Kernel 2: process the compacted uncertain list, scatter exact 1/8 adds.
// ---------------------------------------------------------------------------
__global__ void __launch_bounds__(256)
k_sample2(float* __restrict__ out) {
    const uint32_t n = g_cnt;
    const uint32_t stride = gridDim.x * blockDim.x;
    for (uint32_t k = blockIdx.x * blockDim.x + threadIdx.x; k < n; k += stride) {
        uint2 ent = g_ent[k];
        float l = __uint_as_float(ent.y);
        uint32_t flat = ent.x << 1;      // flat index into (B,K,K,2)
        float g0 = gumbel_from_bits(jax_bits_partitionable(flat));
        float g1 = gumbel_from_bits(jax_bits_partitionable(flat + 1u));
        // argmax over {l+g0, -l+g1}; tie -> index 0 -> sample = 1
        if (__fadd_rn(l, g0) >= __fadd_rn(-l, g1))
            atomicAdd(out + (ent.x & 0x3FFFFu), 0.125f);   // exact multiples of 1/8
    }
}

// ---------------------------------------------------------------------------
extern "C" void kernel_launch(void* const* d_in, const int* in_sizes, int n_in,
                              void* d_out, int out_size) {
    const float* amp = (const float*)d_in[0];   // (B, C, K)
    const float* ph  = (const float*)d_in[1];   // (B, C, K)
    const float* A   = (const float*)d_in[2];   // (K, K)
    const float* wa  = (const float*)d_in[3];   // scalar
    const float* wp  = (const float*)d_in[4];   // scalar
    float* out = (float*)d_out;                  // (K, K)

    void* cnt_addr = nullptr;
    cudaGetSymbolAddress(&cnt_addr, g_cnt);
    cudaMemsetAsync(cnt_addr, 0, sizeof(uint32_t));
    cudaMemsetAsync(out, 0, KQ * KQ * sizeof(float));

    dim3 g1(KQ / IT, BQ);
    k_logit<<<g1, KQ>>>(amp, ph, A, wa, wp);
    k_sample2<<<2048, 256>>>(out);
}

// round 5
// speedup vs baseline: 1.5570x; 1.5570x over previous
#include <cuda_runtime.h>
#include <cstdint>

#define BQ 8
#define CQ 32
#define KQ 512
#define IT 8            // i-rows per block in kernel 1

// Uncertain-decision list (worst case B*K*K entries)
__device__ uint32_t g_cnt;
__device__ uint2    g_ent[BQ * KQ * KQ];   // .x = (b<<18)|(i<<9)|j, .y = logit bits

// ---------------------------------------------------------------------------
// Threefry-2x32, key (0, 42); partitionable scheme: bits(idx) = o0 ^ o1 of
// threefry(key, (0, idx)).
// ---------------------------------------------------------------------------
__device__ __forceinline__ uint32_t rotl32(uint32_t x, int r) {
    return (x << r) | (x >> (32 - r));
}
__device__ __forceinline__ void threefry_0_42(uint32_t x0, uint32_t x1,
                                              uint32_t& o0, uint32_t& o1) {
    const uint32_t ks0 = 0u, ks1 = 42u, ks2 = 0u ^ 42u ^ 0x1BD11BDAu;
    x0 += ks0; x1 += ks1;
    x0 += x1; x1 = rotl32(x1, 13); x1 ^= x0;
    x0 += x1; x1 = rotl32(x1, 15); x1 ^= x0;
    x0 += x1; x1 = rotl32(x1, 26); x1 ^= x0;
    x0 += x1; x1 = rotl32(x1, 6);  x1 ^= x0;
    x0 += ks1; x1 += ks2 + 1u;
    x0 += x1; x1 = rotl32(x1, 17); x1 ^= x0;
    x0 += x1; x1 = rotl32(x1, 29); x1 ^= x0;
    x0 += x1; x1 = rotl32(x1, 16); x1 ^= x0;
    x0 += x1; x1 = rotl32(x1, 24); x1 ^= x0;
    x0 += ks2; x1 += ks0 + 2u;
    x0 += x1; x1 = rotl32(x1, 13); x1 ^= x0;
    x0 += x1; x1 = rotl32(x1, 15); x1 ^= x0;
    x0 += x1; x1 = rotl32(x1, 26); x1 ^= x0;
    x0 += x1; x1 = rotl32(x1, 6);  x1 ^= x0;
    x0 += ks0; x1 += ks1 + 3u;
    x0 += x1; x1 = rotl32(x1, 17); x1 ^= x0;
    x0 += x1; x1 = rotl32(x1, 29); x1 ^= x0;
    x0 += x1; x1 = rotl32(x1, 16); x1 ^= x0;
    x0 += x1; x1 = rotl32(x1, 24); x1 ^= x0;
    x0 += ks1; x1 += ks2 + 4u;
    x0 += x1; x1 = rotl32(x1, 13); x1 ^= x0;
    x0 += x1; x1 = rotl32(x1, 15); x1 ^= x0;
    x0 += x1; x1 = rotl32(x1, 26); x1 ^= x0;
    x0 += x1; x1 = rotl32(x1, 6);  x1 ^= x0;
    x0 += ks2; x1 += ks0 + 5u;
    o0 = x0; o1 = x1;
}
__device__ __forceinline__ uint32_t jax_bits_partitionable(uint32_t idx) {
    uint32_t o0, o1;
    threefry_0_42(0u, idx, o0, o1);
    return o0 ^ o1;
}
__device__ __forceinline__ float gumbel_from_bits(uint32_t bits) {
    float f = __uint_as_float((bits >> 9) | 0x3F800000u) - 1.0f;
    float u = fmaxf(__fadd_rn(f, 1e-10f), 1e-10f);
    return -logf(-logf(u));
}

// ---------------------------------------------------------------------------
// Kernel 1: logits + uncertain-list compaction.
// grid (KQ/IT, BQ), 512 threads (thread = j). Scalar fp (packed f32 is a
// regression on this toolchain — measured rounds 3/4).
// ---------------------------------------------------------------------------
__global__ void __launch_bounds__(KQ)
k_logit(const float* __restrict__ amp, const float* __restrict__ ph,
        const float* __restrict__ A,
        const float* __restrict__ wa_p, const float* __restrict__ wp_p) {
    const int b  = blockIdx.y;
    const int i0 = blockIdx.x * IT;
    const int j  = threadIdx.x;

    __shared__ float    s_ai[CQ][IT];
    __shared__ float    s_pi[CQ][IT];
    __shared__ float    s_max[IT][16];
    __shared__ uint32_t s_cnt;
    __shared__ uint32_t s_base;

    const float wa = wa_p[0];
    const float wp = wp_p[0];
    // wa = wp = 0.5 fast path is bit-exact: rn(0.5*x) exact (pow-2 scale), so
    // f = rn(0.5*ad + 0.5*pd) = 0.5*rn(ad+pd) and rn(f*Ajj) = rn(s*(0.5*Ajj)).
    const bool half = (__float_as_uint(wa) == 0x3F000000u) &&
                      (__float_as_uint(wp) == 0x3F000000u);

    if (threadIdx.x == 0) s_cnt = 0;
    if (threadIdx.x < IT * CQ) {
        int t = threadIdx.x % IT;
        int c = threadIdx.x / IT;
        s_ai[c][t] = amp[(b * CQ + c) * KQ + i0 + t];
        s_pi[c][t] = ph [(b * CQ + c) * KQ + i0 + t];
    }
    __syncthreads();

    const float Ajj = A[j * KQ + j];
    const float Aj2 = __fmul_rn(0.5f, Ajj);   // exact

    float acc[IT];
#pragma unroll
    for (int t = 0; t < IT; t++) acc[t] = 0.0f;

    const float* ap = amp + (size_t)b * CQ * KQ + j;
    const float* pp = ph  + (size_t)b * CQ * KQ + j;

    if (half) {
#pragma unroll 4
        for (int c = 0; c < CQ; c++) {
            float aj = ap[c * KQ];
            float pj = pp[c * KQ];
#pragma unroll
            for (int t = 0; t < IT; t++) {
                float ad = __fsub_rn(s_ai[c][t], aj);
                float pd = __fsub_rn(s_pi[c][t], pj);
                float s  = __fadd_rn(ad, pd);            // = 2*f bit-exactly
                float tt = __fmul_rn(s, Aj2);            // = rn(f*Ajj)
                acc[t]   = __fadd_rn(acc[t], __fmul_rn(tt, tt));
            }
        }
    } else {
#pragma unroll 4
        for (int c = 0; c < CQ; c++) {
            float aj = ap[c * KQ];
            float pj = pp[c * KQ];
#pragma unroll
            for (int t = 0; t < IT; t++) {
                float ad = __fsub_rn(s_ai[c][t], aj);
                float pd = __fsub_rn(s_pi[c][t], pj);
                float f  = __fadd_rn(__fmul_rn(wa, ad), __fmul_rn(wp, pd));
                float tt = __fmul_rn(f, Ajj);
                acc[t]   = __fadd_rn(acc[t], __fmul_rn(tt, tt));
            }
        }
    }

    float ed[IT];
#pragma unroll
    for (int t = 0; t < IT; t++) {
        float d = __fadd_rn(acc[t], 1e-10f);
        float e = __fdiv_rn(1.0f, d);
        if (j == i0 + t) e = 0.0f;           // offdiag mask before the max
        ed[t] = e;
        float m = e;
#pragma unroll
        for (int o = 16; o > 0; o >>= 1)
            m = fmaxf(m, __shfl_xor_sync(0xFFFFFFFFu, m, o));
        if ((threadIdx.x & 31) == 0) s_max[t][threadIdx.x >> 5] = m;
    }
    __syncthreads();

    float lg[IT];
    int nunc = 0;
    int tlist[IT];
#pragma unroll
    for (int t = 0; t < IT; t++) {
        float m = s_max[t][0];
#pragma unroll
        for (int w = 1; w < 16; w++) m = fmaxf(m, s_max[t][w]);

        if (j == i0 + t) {
            // diag: p = 0.99 exactly
            float l = logf(__fdiv_rn(0.99f, __fsub_rn(1.0f, 0.99f)));
            lg[t] = l; tlist[nunc++] = t;
        } else if (ed[t] > __fmul_rn(4.5e-5f, m)) {
            // prefilter: e <= 4.5e-5*m provably implies 2l <= -20 (certain 0);
            // candidates still run the exact div+logf+test, so the list is
            // bit-identical to the unfiltered version.
            float p = __fmul_rn(__fdiv_rn(ed[t], m), 0.99f);
            float l = logf(__fdiv_rn(p, __fsub_rn(1.0f, p)));
            if (!(__fadd_rn(l, l) <= -20.0f)) { lg[t] = l; tlist[nunc] = t; nunc++; }
        }
    }

    int rank = 0;
    if (nunc > 0) rank = atomicAdd(&s_cnt, (uint32_t)nunc);
    __syncthreads();
    if (threadIdx.x == 0 && s_cnt > 0) s_base = atomicAdd(&g_cnt, s_cnt);
    __syncthreads();

    for (int q = 0; q < nunc; q++) {
        int t = tlist[q];
        uint2 ent;
        ent.x = ((uint32_t)b << 18) | ((uint32_t)(i0 + t) << 9) | (uint32_t)j;
        ent.y = __float_as_uint(lg[t]);
        g_ent[s_base + rank + q] = ent;
    }
}

// ---------------------------------------------------------------------------
// Kernel 2: process the compacted uncertain list, scatter exact 1/8 adds.
// ---------------------------------------------------------------------------
__global__ void __launch_bounds__(256)
k_sample2(float* __restrict__ out) {
    const uint32_t n = g_cnt;
    const uint32_t stride = gridDim.x * blockDim.x;
    for (uint32_t k = blockIdx.x * blockDim.x + threadIdx.x; k < n; k += stride) {
        uint2 ent = g_ent[k];
        float l = __uint_as_float(ent.y);
        uint32_t flat = ent.x << 1;      // flat index into (B,K,K,2)
        float g0 = gumbel_from_bits(jax_bits_partitionable(flat));
        float g1 = gumbel_from_bits(jax_bits_partitionable(flat + 1u));
        // argmax over {l+g0, -l+g1}; tie -> index 0 -> sample = 1
        if (__fadd_rn(l, g0) >= __fadd_rn(-l, g1))
            atomicAdd(out + (ent.x & 0x3FFFFu), 0.125f);   // exact multiples of 1/8
    }
}

// ---------------------------------------------------------------------------
extern "C" void kernel_launch(void* const* d_in, const int* in_sizes, int n_in,
                              void* d_out, int out_size) {
    const float* amp = (const float*)d_in[0];   // (B, C, K)
    const float* ph  = (const float*)d_in[1];   // (B, C, K)
    const float* A   = (const float*)d_in[2];   // (K, K)
    const float* wa  = (const float*)d_in[3];   // scalar
    const float* wp  = (const float*)d_in[4];   // scalar
    float* out = (float*)d_out;                  // (K, K)

    void* cnt_addr = nullptr;
    cudaGetSymbolAddress(&cnt_addr, g_cnt);
    cudaMemsetAsync(cnt_addr, 0, sizeof(uint32_t));
    cudaMemsetAsync(out, 0, KQ * KQ * sizeof(float));

    dim3 g1(KQ / IT, BQ);
    k_logit<<<g1, KQ>>>(amp, ph, A, wa, wp);
    k_sample2<<<1024, 256>>>(out);
}

// round 6
// speedup vs baseline: 1.7224x; 1.1062x over previous
#include <cuda_runtime.h>
#include <cstdint>

#define BQ 8
#define CQ 32
#define KQ 512
#define IT 4            // i-rows per block in kernel 1

// Uncertain-decision list (worst case B*K*K entries)
__device__ uint32_t g_cnt;
__device__ uint2    g_ent[BQ * KQ * KQ];   // .x = (b<<18)|(i<<9)|j, .y = logit bits

// ---------------------------------------------------------------------------
// Threefry-2x32, key (0, 42); partitionable scheme: bits(idx) = o0 ^ o1 of
// threefry(key, (0, idx)).
// ---------------------------------------------------------------------------
__device__ __forceinline__ uint32_t rotl32(uint32_t x, int r) {
    return (x << r) | (x >> (32 - r));
}
__device__ __forceinline__ void threefry_0_42(uint32_t x0, uint32_t x1,
                                              uint32_t& o0, uint32_t& o1) {
    const uint32_t ks0 = 0u, ks1 = 42u, ks2 = 0u ^ 42u ^ 0x1BD11BDAu;
    x0 += ks0; x1 += ks1;
    x0 += x1; x1 = rotl32(x1, 13); x1 ^= x0;
    x0 += x1; x1 = rotl32(x1, 15); x1 ^= x0;
    x0 += x1; x1 = rotl32(x1, 26); x1 ^= x0;
    x0 += x1; x1 = rotl32(x1, 6);  x1 ^= x0;
    x0 += ks1; x1 += ks2 + 1u;
    x0 += x1; x1 = rotl32(x1, 17); x1 ^= x0;
    x0 += x1; x1 = rotl32(x1, 29); x1 ^= x0;
    x0 += x1; x1 = rotl32(x1, 16); x1 ^= x0;
    x0 += x1; x1 = rotl32(x1, 24); x1 ^= x0;
    x0 += ks2; x1 += ks0 + 2u;
    x0 += x1; x1 = rotl32(x1, 13); x1 ^= x0;
    x0 += x1; x1 = rotl32(x1, 15); x1 ^= x0;
    x0 += x1; x1 = rotl32(x1, 26); x1 ^= x0;
    x0 += x1; x1 = rotl32(x1, 6);  x1 ^= x0;
    x0 += ks0; x1 += ks1 + 3u;
    x0 += x1; x1 = rotl32(x1, 17); x1 ^= x0;
    x0 += x1; x1 = rotl32(x1, 29); x1 ^= x0;
    x0 += x1; x1 = rotl32(x1, 16); x1 ^= x0;
    x0 += x1; x1 = rotl32(x1, 24); x1 ^= x0;
    x0 += ks1; x1 += ks2 + 4u;
    x0 += x1; x1 = rotl32(x1, 13); x1 ^= x0;
    x0 += x1; x1 = rotl32(x1, 15); x1 ^= x0;
    x0 += x1; x1 = rotl32(x1, 26); x1 ^= x0;
    x0 += x1; x1 = rotl32(x1, 6);  x1 ^= x0;
    x0 += ks2; x1 += ks0 + 5u;
    o0 = x0; o1 = x1;
}
__device__ __forceinline__ uint32_t jax_bits_partitionable(uint32_t idx) {
    uint32_t o0, o1;
    threefry_0_42(0u, idx, o0, o1);
    return o0 ^ o1;
}
__device__ __forceinline__ float gumbel_from_bits(uint32_t bits) {
    float f = __uint_as_float((bits >> 9) | 0x3F800000u) - 1.0f;
    float u = fmaxf(__fadd_rn(f, 1e-10f), 1e-10f);
    return -logf(-logf(u));
}

// add-class ops as FFMA with +-1.0 immediate multiplier (rt_SMSP = 1):
//   rn(a - b) == fma(b, -1.0, a)   (b * -1.0 exact)
//   rn(a + b) == fma(a,  1.0, b)   (a *  1.0 exact)
__device__ __forceinline__ float fsub_via_fma(float a, float b) {
    return __fmaf_rn(b, -1.0f, a);
}
__device__ __forceinline__ float fadd_via_fma(float a, float b) {
    return __fmaf_rn(a, 1.0f, b);
}

// ---------------------------------------------------------------------------
// Kernel 1: logits + uncertain-list compaction.
// grid (KQ/IT, BQ) = (128, 8), 512 threads (thread = j).
// ---------------------------------------------------------------------------
__global__ void __launch_bounds__(KQ)
k_logit(const float* __restrict__ amp, const float* __restrict__ ph,
        const float* __restrict__ A,
        const float* __restrict__ wa_p, const float* __restrict__ wp_p) {
    const int b  = blockIdx.y;
    const int i0 = blockIdx.x * IT;
    const int j  = threadIdx.x;

    __shared__ float    s_ai[CQ][IT];
    __shared__ float    s_pi[CQ][IT];
    __shared__ float    s_max[IT][16];
    __shared__ uint32_t s_cnt;
    __shared__ uint32_t s_base;

    const float wa = wa_p[0];
    const float wp = wp_p[0];
    // wa = wp = 0.5 fast path is bit-exact: rn(0.5*x) exact (pow-2 scale), so
    // f = rn(0.5*ad + 0.5*pd) = 0.5*rn(ad+pd) and rn(f*Ajj) = rn(s*(0.5*Ajj)).
    const bool half = (__float_as_uint(wa) == 0x3F000000u) &&
                      (__float_as_uint(wp) == 0x3F000000u);

    if (threadIdx.x == 0) s_cnt = 0;
    if (threadIdx.x < IT * CQ) {
        int t = threadIdx.x % IT;
        int c = threadIdx.x / IT;
        s_ai[c][t] = amp[(b * CQ + c) * KQ + i0 + t];
        s_pi[c][t] = ph [(b * CQ + c) * KQ + i0 + t];
    }
    __syncthreads();

    const float Ajj = A[j * KQ + j];
    const float Aj2 = __fmul_rn(0.5f, Ajj);   // exact

    float acc[IT];
#pragma unroll
    for (int t = 0; t < IT; t++) acc[t] = 0.0f;

    const float* ap = amp + (size_t)b * CQ * KQ + j;
    const float* pp = ph  + (size_t)b * CQ * KQ + j;

    if (half) {
#pragma unroll 8
        for (int c = 0; c < CQ; c++) {
            float aj = ap[c * KQ];
            float pj = pp[c * KQ];
#pragma unroll
            for (int t = 0; t < IT; t++) {
                float ad = fsub_via_fma(s_ai[c][t], aj);   // rn(ai - aj)
                float pd = fsub_via_fma(s_pi[c][t], pj);   // rn(pi - pj)
                float s  = fadd_via_fma(ad, pd);           // = 2*f bit-exactly
                float tt = __fmul_rn(s, Aj2);              // = rn(f*Ajj)
                float sq = __fmul_rn(tt, tt);
                acc[t]   = fadd_via_fma(sq, acc[t]);
            }
        }
    } else {
#pragma unroll 8
        for (int c = 0; c < CQ; c++) {
            float aj = ap[c * KQ];
            float pj = pp[c * KQ];
#pragma unroll
            for (int t = 0; t < IT; t++) {
                float ad = fsub_via_fma(s_ai[c][t], aj);
                float pd = fsub_via_fma(s_pi[c][t], pj);
                float f  = fadd_via_fma(__fmul_rn(wa, ad), __fmul_rn(wp, pd));
                float tt = __fmul_rn(f, Ajj);
                float sq = __fmul_rn(tt, tt);
                acc[t]   = fadd_via_fma(sq, acc[t]);
            }
        }
    }

    float ed[IT];
#pragma unroll
    for (int t = 0; t < IT; t++) {
        float d = __fadd_rn(acc[t], 1e-10f);
        float e = __fdiv_rn(1.0f, d);
        if (j == i0 + t) e = 0.0f;           // offdiag mask before the max
        ed[t] = e;
        float m = e;
#pragma unroll
        for (int o = 16; o > 0; o >>= 1)
            m = fmaxf(m, __shfl_xor_sync(0xFFFFFFFFu, m, o));
        if ((threadIdx.x & 31) == 0) s_max[t][threadIdx.x >> 5] = m;
    }
    __syncthreads();

    float lg[IT];
    int nunc = 0;
    int tlist[IT];
#pragma unroll
    for (int t = 0; t < IT; t++) {
        float m = s_max[t][0];
#pragma unroll
        for (int w = 1; w < 16; w++) m = fmaxf(m, s_max[t][w]);

        if (j == i0 + t) {
            // diag: p = 0.99 exactly
            float l = logf(__fdiv_rn(0.99f, __fsub_rn(1.0f, 0.99f)));
            lg[t] = l; tlist[nunc++] = t;
        } else if (ed[t] > __fmul_rn(4.5e-5f, m)) {
            // prefilter: e <= 4.5e-5*m provably implies 2l <= -20 (certain 0);
            // candidates still run the exact div+logf+test, so the list is
            // bit-identical to the unfiltered version.
            float p = __fmul_rn(__fdiv_rn(ed[t], m), 0.99f);
            float l = logf(__fdiv_rn(p, __fsub_rn(1.0f, p)));
            if (!(__fadd_rn(l, l) <= -20.0f)) { lg[t] = l; tlist[nunc] = t; nunc++; }
        }
    }

    int rank = 0;
    if (nunc > 0) rank = atomicAdd(&s_cnt, (uint32_t)nunc);
    __syncthreads();
    if (threadIdx.x == 0 && s_cnt > 0) s_base = atomicAdd(&g_cnt, s_cnt);
    __syncthreads();

    for (int q = 0; q < nunc; q++) {
        int t = tlist[q];
        uint2 ent;
        ent.x = ((uint32_t)b << 18) | ((uint32_t)(i0 + t) << 9) | (uint32_t)j;
        ent.y = __float_as_uint(lg[t]);
        g_ent[s_base + rank + q] = ent;
    }
}

// ---------------------------------------------------------------------------
// Kernel 2: process the compacted uncertain list, scatter exact 1/8 adds.
// ---------------------------------------------------------------------------
__global__ void __launch_bounds__(256)
k_sample2(float* __restrict__ out) {
    const uint32_t n = g_cnt;
    const uint32_t stride = gridDim.x * blockDim.x;
    for (uint32_t k = blockIdx.x * blockDim.x + threadIdx.x; k < n; k += stride) {
        uint2 ent = g_ent[k];
        float l = __uint_as_float(ent.y);
        uint32_t flat = ent.x << 1;      // flat index into (B,K,K,2)
        float g0 = gumbel_from_bits(jax_bits_partitionable(flat));
        float g1 = gumbel_from_bits(jax_bits_partitionable(flat + 1u));
        // argmax over {l+g0, -l+g1}; tie -> index 0 -> sample = 1
        if (__fadd_rn(l, g0) >= __fadd_rn(-l, g1))
            atomicAdd(out + (ent.x & 0x3FFFFu), 0.125f);   // exact multiples of 1/8
    }
}

// ---------------------------------------------------------------------------
extern "C" void kernel_launch(void* const* d_in, const int* in_sizes, int n_in,
                              void* d_out, int out_size) {
    const float* amp = (const float*)d_in[0];   // (B, C, K)
    const float* ph  = (const float*)d_in[1];   // (B, C, K)
    const float* A   = (const float*)d_in[2];   // (K, K)
    const float* wa  = (const float*)d_in[3];   // scalar
    const float* wp  = (const float*)d_in[4];   // scalar
    float* out = (float*)d_out;                  // (K, K)

    void* cnt_addr = nullptr;
    cudaGetSymbolAddress(&cnt_addr, g_cnt);
    cudaMemsetAsync(cnt_addr, 0, sizeof(uint32_t));
    cudaMemsetAsync(out, 0, KQ * KQ * sizeof(float));

    dim3 g1(KQ / IT, BQ);
    k_logit<<<g1, KQ>>>(amp, ph, A, wa, wp);
    k_sample2<<<1024, 256>>>(out);
}